// round 1
// baseline (speedup 1.0000x reference)
#include <cuda_runtime.h>
#include <math.h>

// Problem dims (fixed per setup_inputs)
#define BB 8
#define NN_ 2048
#define DD 1024
#define HH 4096
#define BN (BB * NN_)   // 16384

// ---------------- scratch (static device globals; no allocation) ----------------
__device__ float g_X   [(size_t)BN * DD];      // q_prob - k_prob ; later reused as (v - attn_feat)
__device__ float g_L   [(size_t)BN * DD];      // log(q_prob) - log(k_prob)
__device__ float g_attn[(size_t)BB * NN_ * NN_]; // sid logits -> softmax (in place)
__device__ float g_af  [(size_t)BN * DD];      // attn_feat
__device__ float g_fd  [(size_t)BN * DD];      // f_diff
__device__ float g_h   [(size_t)BN * DD];      // layernorm(f_diff)
__device__ float g_act [(size_t)BN * HH];      // gelu(h@W1^T + b1)
__device__ float g_out [(size_t)BN * DD];      // mlp + f_diff (pre final LN)

// ---------------- reductions ----------------
__device__ __forceinline__ float block_sum_256(float v, float* sbuf) {
    #pragma unroll
    for (int o = 16; o; o >>= 1) v += __shfl_xor_sync(0xffffffffu, v, o);
    int w = threadIdx.x >> 5;
    if ((threadIdx.x & 31) == 0) sbuf[w] = v;
    __syncthreads();
    if (threadIdx.x < 8) {
        v = sbuf[threadIdx.x];
        #pragma unroll
        for (int o = 4; o; o >>= 1) v += __shfl_xor_sync(0xffu, v, o);
        if (threadIdx.x == 0) sbuf[0] = v;
    }
    __syncthreads();
    float r = sbuf[0];
    __syncthreads();
    return r;
}

// ---------------- prob / log-ratio kernel ----------------
// One block per (b,n) row. Computes X = q_prob - k_prob, L = log q_prob - log k_prob.
__global__ void __launch_bounds__(256)
prob_kernel(const float* __restrict__ q, const float* __restrict__ k,
            float* __restrict__ X, float* __restrict__ L)
{
    __shared__ float sbuf[8];
    size_t base = (size_t)blockIdx.x * DD;
    int t = threadIdx.x;
    float tq[4], tk[4];
    float sq = 0.f, sk = 0.f;
    #pragma unroll
    for (int l = 0; l < 4; ++l) {
        int i = t + l * 256;
        tq[l] = tanhf(q[base + i]) * 0.499f + 0.5f;
        tk[l] = tanhf(k[base + i]) * 0.499f + 0.5f;
        sq += tq[l]; sk += tk[l];
    }
    float sumq = block_sum_256(sq, sbuf);
    float sumk = block_sum_256(sk, sbuf);
    float iq = 1.f / (sumq + 1e-8f);
    float ik = 1.f / (sumk + 1e-8f);
    #pragma unroll
    for (int l = 0; l < 4; ++l) {
        int i = t + l * 256;
        float pq = fmaxf(tq[l] * iq, 1e-8f);
        float pk = fmaxf(tk[l] * ik, 1e-8f);
        X[base + i] = pq - pk;
        L[base + i] = logf(pq) - logf(pk);
    }
}

// ---------------- softmax over last dim (row length 2048), in place ----------------
__global__ void __launch_bounds__(512)
softmax_kernel(float* __restrict__ A)
{
    __shared__ float sbuf[16];
    size_t base = (size_t)blockIdx.x * NN_;
    int t = threadIdx.x;
    float x[4];
    float mx = -1e30f;
    #pragma unroll
    for (int l = 0; l < 4; ++l) { x[l] = A[base + t + l * 512]; mx = fmaxf(mx, x[l]); }
    #pragma unroll
    for (int o = 16; o; o >>= 1) mx = fmaxf(mx, __shfl_xor_sync(0xffffffffu, mx, o));
    int w = t >> 5;
    if ((t & 31) == 0) sbuf[w] = mx;
    __syncthreads();
    if (t < 16) {
        mx = sbuf[t];
        #pragma unroll
        for (int o = 8; o; o >>= 1) mx = fmaxf(mx, __shfl_xor_sync(0xffffu, mx, o));
        if (t == 0) sbuf[0] = mx;
    }
    __syncthreads();
    mx = sbuf[0];
    __syncthreads();

    float s = 0.f;
    #pragma unroll
    for (int l = 0; l < 4; ++l) { x[l] = expf(x[l] - mx); s += x[l]; }
    #pragma unroll
    for (int o = 16; o; o >>= 1) s += __shfl_xor_sync(0xffffffffu, s, o);
    if ((t & 31) == 0) sbuf[w] = s;
    __syncthreads();
    if (t < 16) {
        s = sbuf[t];
        #pragma unroll
        for (int o = 8; o; o >>= 1) s += __shfl_xor_sync(0xffffu, s, o);
        if (t == 0) sbuf[0] = s;
    }
    __syncthreads();
    float inv = 1.f / sbuf[0];
    #pragma unroll
    for (int l = 0; l < 4; ++l) A[base + t + l * 512] = x[l] * inv;
}

// ---------------- layernorm (row length 1024) ----------------
__global__ void __launch_bounds__(256)
layernorm_kernel(const float* __restrict__ in, const float* __restrict__ g,
                 const float* __restrict__ b, float* __restrict__ out)
{
    __shared__ float sbuf[8];
    size_t base = (size_t)blockIdx.x * DD;
    int t = threadIdx.x;
    float x[4]; float s = 0.f;
    #pragma unroll
    for (int l = 0; l < 4; ++l) { x[l] = in[base + t + l * 256]; s += x[l]; }
    float mean = block_sum_256(s, sbuf) * (1.f / DD);
    float vs = 0.f;
    #pragma unroll
    for (int l = 0; l < 4; ++l) { float d = x[l] - mean; vs += d * d; }
    float var = block_sum_256(vs, sbuf) * (1.f / DD);
    float r = rsqrtf(var + 1e-5f);
    #pragma unroll
    for (int l = 0; l < 4; ++l) {
        int i = t + l * 256;
        out[base + i] = (x[l] - mean) * r * g[i] + b[i];
    }
}

// ---------------- elementwise c = a - b (float4) ----------------
__global__ void __launch_bounds__(256)
sub_kernel(const float* __restrict__ a, const float* __restrict__ b,
           float* __restrict__ c, size_t n4)
{
    size_t i = (size_t)blockIdx.x * blockDim.x + threadIdx.x;
    if (i < n4) {
        float4 va = ((const float4*)a)[i];
        float4 vb = ((const float4*)b)[i];
        ((float4*)c)[i] = make_float4(va.x - vb.x, va.y - vb.y, va.z - vb.z, va.w - vb.w);
    }
}

// ---------------- generic tiled SGEMM ----------------
// C[m,n] = alpha * sum_k A[m,k] * (TB ? B[n,k] : B[k,n])   (+bias[n]) (gelu) (+addend[m,n])
// Block tile 128x128, K-tile 16, 256 threads, 8x8 per-thread micro-tile.
// Requires M%128==0, N%128==0, K%16==0 (all shapes here satisfy this).
template<bool TB>
__global__ void __launch_bounds__(256)
gemm_tile(const float* __restrict__ A, const float* __restrict__ B,
          float* __restrict__ C,
          int M, int N, int K,
          size_t sA, size_t sB, size_t sC,
          float alpha,
          const float* __restrict__ bias,
          const float* __restrict__ addend,
          int do_gelu)
{
    __shared__ float As[16][132];
    __shared__ float Bs[16][132];
    const int t  = threadIdx.x;
    const int m0 = blockIdx.y * 128;
    const int n0 = blockIdx.x * 128;
    const float* Ab = A + (size_t)blockIdx.z * sA;
    const float* Bp = B + (size_t)blockIdx.z * sB;
    float*       Cb = C + (size_t)blockIdx.z * sC;
    const int ty = t >> 4, tx = t & 15;

    float acc[8][8];
    #pragma unroll
    for (int i = 0; i < 8; ++i)
        #pragma unroll
        for (int j = 0; j < 8; ++j) acc[i][j] = 0.f;

    for (int k0 = 0; k0 < K; k0 += 16) {
        // Load A tile (128 rows x 16 k), store transposed As[k][m]
        #pragma unroll
        for (int l = 0; l < 2; ++l) {
            int idx = t + l * 256;
            int r = idx >> 2, c = (idx & 3) << 2;
            float4 va = *(const float4*)(Ab + (size_t)(m0 + r) * K + k0 + c);
            As[c + 0][r] = va.x; As[c + 1][r] = va.y;
            As[c + 2][r] = va.z; As[c + 3][r] = va.w;
        }
        if (TB) {
            // B row-major [N,K]; tile rows n0..n0+127, cols k0..k0+15
            #pragma unroll
            for (int l = 0; l < 2; ++l) {
                int idx = t + l * 256;
                int r = idx >> 2, c = (idx & 3) << 2;
                float4 vb = *(const float4*)(Bp + (size_t)(n0 + r) * K + k0 + c);
                Bs[c + 0][r] = vb.x; Bs[c + 1][r] = vb.y;
                Bs[c + 2][r] = vb.z; Bs[c + 3][r] = vb.w;
            }
        } else {
            // B row-major [K,N]; tile rows k0..k0+15, cols n0..n0+127
            #pragma unroll
            for (int l = 0; l < 2; ++l) {
                int idx = t + l * 256;
                int r = idx >> 5, c = (idx & 31) << 2;
                float4 vb = *(const float4*)(Bp + (size_t)(k0 + r) * N + n0 + c);
                *(float4*)&Bs[r][c] = vb;
            }
        }
        __syncthreads();

        #pragma unroll
        for (int kk = 0; kk < 16; ++kk) {
            float a[8], bv[8];
            float4 a0 = *(const float4*)&As[kk][ty * 8];
            float4 a1 = *(const float4*)&As[kk][ty * 8 + 4];
            float4 b0 = *(const float4*)&Bs[kk][tx * 8];
            float4 b1 = *(const float4*)&Bs[kk][tx * 8 + 4];
            a[0]=a0.x; a[1]=a0.y; a[2]=a0.z; a[3]=a0.w;
            a[4]=a1.x; a[5]=a1.y; a[6]=a1.z; a[7]=a1.w;
            bv[0]=b0.x; bv[1]=b0.y; bv[2]=b0.z; bv[3]=b0.w;
            bv[4]=b1.x; bv[5]=b1.y; bv[6]=b1.z; bv[7]=b1.w;
            #pragma unroll
            for (int i = 0; i < 8; ++i)
                #pragma unroll
                for (int j = 0; j < 8; ++j)
                    acc[i][j] = fmaf(a[i], bv[j], acc[i][j]);
        }
        __syncthreads();
    }

    // Epilogue: alpha -> +bias -> gelu -> +addend -> store
    #pragma unroll
    for (int i = 0; i < 8; ++i) {
        int m = m0 + ty * 8 + i;
        #pragma unroll
        for (int j = 0; j < 8; ++j) {
            int n = n0 + tx * 8 + j;
            float v = acc[i][j] * alpha;
            if (bias)    v += bias[n];
            if (do_gelu) v = 0.5f * v * (1.0f + erff(v * 0.7071067811865475f));
            if (addend)  v += addend[(size_t)blockIdx.z * sC + (size_t)m * N + n];
            Cb[(size_t)m * N + n] = v;
        }
    }
}

// ---------------- launch ----------------
extern "C" void kernel_launch(void* const* d_in, const int* in_sizes, int n_in,
                              void* d_out, int out_size)
{
    const float* q      = (const float*)d_in[0];
    const float* k      = (const float*)d_in[1];
    const float* v      = (const float*)d_in[2];
    const float* W_diff = (const float*)d_in[3];
    const float* b_diff = (const float*)d_in[4];
    const float* ln_g   = (const float*)d_in[5];
    const float* ln_b   = (const float*)d_in[6];
    const float* W1     = (const float*)d_in[7];
    const float* b1     = (const float*)d_in[8];
    const float* W2     = (const float*)d_in[9];
    const float* b2     = (const float*)d_in[10];
    float* out = (float*)d_out;

    float *pX, *pL, *pAttn, *pAf, *pFd, *pH, *pAct, *pOut;
    cudaGetSymbolAddress((void**)&pX,    g_X);
    cudaGetSymbolAddress((void**)&pL,    g_L);
    cudaGetSymbolAddress((void**)&pAttn, g_attn);
    cudaGetSymbolAddress((void**)&pAf,   g_af);
    cudaGetSymbolAddress((void**)&pFd,   g_fd);
    cudaGetSymbolAddress((void**)&pH,    g_h);
    cudaGetSymbolAddress((void**)&pAct,  g_act);
    cudaGetSymbolAddress((void**)&pOut,  g_out);

    const size_t sND = (size_t)NN_ * DD;   // per-batch stride of [N,D]
    const size_t sNN = (size_t)NN_ * NN_;  // per-batch stride of [N,N]

    // 1) q_prob/k_prob -> X, L
    prob_kernel<<<BN, 256>>>(q, k, pX, pL);

    // 2) sid logits: attn = -(X @ L^T) / 32   (batched NT)
    gemm_tile<true><<<dim3(NN_ / 128, NN_ / 128, BB), 256>>>(
        pX, pL, pAttn, NN_, NN_, DD, sND, sND, sNN,
        -1.0f / 32.0f, nullptr, nullptr, 0);

    // 3) softmax rows (in place)
    softmax_kernel<<<BN, 512>>>(pAttn);

    // 4) attn_feat = attn @ v   (batched NN)
    gemm_tile<false><<<dim3(DD / 128, NN_ / 128, BB), 256>>>(
        pAttn, v, pAf, NN_, DD, NN_, sNN, sND, sND,
        1.0f, nullptr, nullptr, 0);

    // 5) vd = v - attn_feat  (reuse g_X)
    {
        size_t n4 = (size_t)BN * DD / 4;
        sub_kernel<<<(unsigned)((n4 + 255) / 256), 256>>>(v, pAf, pX, n4);
    }

    // 6) f_diff = vd @ W_diff^T + b_diff + q
    gemm_tile<true><<<dim3(DD / 128, BN / 128, 1), 256>>>(
        pX, W_diff, pFd, BN, DD, DD, 0, 0, 0,
        1.0f, b_diff, q, 0);

    // 7) h = LN(f_diff)
    layernorm_kernel<<<BN, 256>>>(pFd, ln_g, ln_b, pH);

    // 8) act = gelu(h @ W1^T + b1)
    gemm_tile<true><<<dim3(HH / 128, BN / 128, 1), 256>>>(
        pH, W1, pAct, BN, HH, DD, 0, 0, 0,
        1.0f, b1, nullptr, 1);

    // 9) out_pre = act @ W2^T + b2 + f_diff
    gemm_tile<true><<<dim3(DD / 128, BN / 128, 1), 256>>>(
        pAct, W2, pOut, BN, DD, HH, 0, 0, 0,
        1.0f, b2, pFd, 0);

    // 10) final LN -> d_out
    layernorm_kernel<<<BN, 256>>>(pOut, ln_g, ln_b, out);
}

// round 2
// speedup vs baseline: 2.8854x; 2.8854x over previous
#include <cuda_runtime.h>
#include <math.h>

// Problem dims (fixed per setup_inputs)
#define BB 8
#define NN_ 2048
#define DD 1024
#define HH 4096
#define BN (BB * NN_)   // 16384

// ---------------- scratch (static device globals; no allocation) ----------------
__device__ __align__(256) float g_X   [(size_t)BN * DD];
__device__ __align__(256) float g_L   [(size_t)BN * DD];
__device__ __align__(256) float g_attn[(size_t)BB * NN_ * NN_];
__device__ __align__(256) float g_af  [(size_t)BN * DD];
__device__ __align__(256) float g_fd  [(size_t)BN * DD];
__device__ __align__(256) float g_h   [(size_t)BN * DD];
__device__ __align__(256) float g_act [(size_t)BN * HH];
__device__ __align__(256) float g_out [(size_t)BN * DD];

// ---------------- reductions ----------------
__device__ __forceinline__ float block_sum_256(float v, float* sbuf) {
    #pragma unroll
    for (int o = 16; o; o >>= 1) v += __shfl_xor_sync(0xffffffffu, v, o);
    int w = threadIdx.x >> 5;
    if ((threadIdx.x & 31) == 0) sbuf[w] = v;
    __syncthreads();
    if (threadIdx.x < 8) {
        v = sbuf[threadIdx.x];
        #pragma unroll
        for (int o = 4; o; o >>= 1) v += __shfl_xor_sync(0xffu, v, o);
        if (threadIdx.x == 0) sbuf[0] = v;
    }
    __syncthreads();
    float r = sbuf[0];
    __syncthreads();
    return r;
}

// ---------------- prob / log-ratio kernel ----------------
__global__ void __launch_bounds__(256)
prob_kernel(const float* __restrict__ q, const float* __restrict__ k,
            float* __restrict__ X, float* __restrict__ L)
{
    __shared__ float sbuf[8];
    size_t base = (size_t)blockIdx.x * DD;
    int t = threadIdx.x;
    float tq[4], tk[4];
    float sq = 0.f, sk = 0.f;
    #pragma unroll
    for (int l = 0; l < 4; ++l) {
        int i = t + l * 256;
        tq[l] = tanhf(q[base + i]) * 0.499f + 0.5f;
        tk[l] = tanhf(k[base + i]) * 0.499f + 0.5f;
        sq += tq[l]; sk += tk[l];
    }
    float sumq = block_sum_256(sq, sbuf);
    float sumk = block_sum_256(sk, sbuf);
    float iq = 1.f / (sumq + 1e-8f);
    float ik = 1.f / (sumk + 1e-8f);
    #pragma unroll
    for (int l = 0; l < 4; ++l) {
        int i = t + l * 256;
        float pq = fmaxf(tq[l] * iq, 1e-8f);
        float pk = fmaxf(tk[l] * ik, 1e-8f);
        X[base + i] = pq - pk;
        L[base + i] = logf(pq) - logf(pk);
    }
}

// ---------------- softmax over last dim (row length 2048), in place ----------------
__global__ void __launch_bounds__(512)
softmax_kernel(float* __restrict__ A)
{
    __shared__ float sbuf[16];
    size_t base = (size_t)blockIdx.x * NN_;
    int t = threadIdx.x;
    float x[4];
    float mx = -1e30f;
    #pragma unroll
    for (int l = 0; l < 4; ++l) { x[l] = A[base + t + l * 512]; mx = fmaxf(mx, x[l]); }
    #pragma unroll
    for (int o = 16; o; o >>= 1) mx = fmaxf(mx, __shfl_xor_sync(0xffffffffu, mx, o));
    int w = t >> 5;
    if ((t & 31) == 0) sbuf[w] = mx;
    __syncthreads();
    if (t < 16) {
        mx = sbuf[t];
        #pragma unroll
        for (int o = 8; o; o >>= 1) mx = fmaxf(mx, __shfl_xor_sync(0xffffu, mx, o));
        if (t == 0) sbuf[0] = mx;
    }
    __syncthreads();
    mx = sbuf[0];
    __syncthreads();

    float s = 0.f;
    #pragma unroll
    for (int l = 0; l < 4; ++l) { x[l] = expf(x[l] - mx); s += x[l]; }
    #pragma unroll
    for (int o = 16; o; o >>= 1) s += __shfl_xor_sync(0xffffffffu, s, o);
    if ((t & 31) == 0) sbuf[w] = s;
    __syncthreads();
    if (t < 16) {
        s = sbuf[t];
        #pragma unroll
        for (int o = 8; o; o >>= 1) s += __shfl_xor_sync(0xffffu, s, o);
        if (t == 0) sbuf[0] = s;
    }
    __syncthreads();
    float inv = 1.f / sbuf[0];
    #pragma unroll
    for (int l = 0; l < 4; ++l) A[base + t + l * 512] = x[l] * inv;
}

// ---------------- layernorm (row length 1024) ----------------
__global__ void __launch_bounds__(256)
layernorm_kernel(const float* __restrict__ in, const float* __restrict__ g,
                 const float* __restrict__ b, float* __restrict__ out)
{
    __shared__ float sbuf[8];
    size_t base = (size_t)blockIdx.x * DD;
    int t = threadIdx.x;
    float x[4]; float s = 0.f;
    #pragma unroll
    for (int l = 0; l < 4; ++l) { x[l] = in[base + t + l * 256]; s += x[l]; }
    float mean = block_sum_256(s, sbuf) * (1.f / DD);
    float vs = 0.f;
    #pragma unroll
    for (int l = 0; l < 4; ++l) { float d = x[l] - mean; vs += d * d; }
    float var = block_sum_256(vs, sbuf) * (1.f / DD);
    float r = rsqrtf(var + 1e-5f);
    #pragma unroll
    for (int l = 0; l < 4; ++l) {
        int i = t + l * 256;
        out[base + i] = (x[l] - mean) * r * g[i] + b[i];
    }
}

// ---------------- elementwise c = a - b (float4) ----------------
__global__ void __launch_bounds__(256)
sub_kernel(const float* __restrict__ a, const float* __restrict__ b,
           float* __restrict__ c, size_t n4)
{
    size_t i = (size_t)blockIdx.x * blockDim.x + threadIdx.x;
    if (i < n4) {
        float4 va = ((const float4*)a)[i];
        float4 vb = ((const float4*)b)[i];
        ((float4*)c)[i] = make_float4(va.x - vb.x, va.y - vb.y, va.z - vb.z, va.w - vb.w);
    }
}

// ---------------- tf32 tensor-core GEMM ----------------
// C[m,n] = alpha * sum_k A[m,k] * (TB ? B[n,k] : B[k,n])  (+bias[n]) (gelu) (+addend[m,n])
// 128x128 block tile, kTile=16, 3-stage cp.async pipeline, 8 warps (2x4),
// warp tile 64x32 via mma.sync.m16n8k8.tf32.
// Requires M%128==0, N%128==0, K%16==0 (all shapes here satisfy this).

#define STAGES 3
#define ASTR 20          // smem stride for [row][k] layouts (A, and B when TB)
#define BSTR_NN 136      // smem stride for [k][n] layout (B when !TB), bank-clean: 8k+n
#define A_STAGE_FLTS (128 * ASTR)       // 2560
#define B_STAGE_FLTS (128 * ASTR)       // 2560 (covers both layouts; NN needs 16*136=2176)
#define SMEM_FLTS (STAGES * (A_STAGE_FLTS + B_STAGE_FLTS))
#define SMEM_BYTES (SMEM_FLTS * 4)      // 61440

__device__ __forceinline__ void cp_async16(void* s, const void* g) {
    unsigned sa = (unsigned)__cvta_generic_to_shared(s);
    asm volatile("cp.async.cg.shared.global [%0], [%1], 16;\n" :: "r"(sa), "l"(g));
}
__device__ __forceinline__ void cp_commit() { asm volatile("cp.async.commit_group;\n" ::: "memory"); }
template<int NW> __device__ __forceinline__ void cp_wait() {
    asm volatile("cp.async.wait_group %0;\n" :: "n"(NW) : "memory");
}
__device__ __forceinline__ unsigned f2tf32(float x) {
    unsigned r; asm("cvt.rna.tf32.f32 %0, %1;" : "=r"(r) : "f"(x)); return r;
}
__device__ __forceinline__ void mma_tf32(float c[4], const unsigned a[4], const unsigned b[2]) {
    asm volatile(
        "mma.sync.aligned.m16n8k8.row.col.f32.tf32.tf32.f32 "
        "{%0,%1,%2,%3}, {%4,%5,%6,%7}, {%8,%9}, {%0,%1,%2,%3};"
        : "+f"(c[0]), "+f"(c[1]), "+f"(c[2]), "+f"(c[3])
        : "r"(a[0]), "r"(a[1]), "r"(a[2]), "r"(a[3]), "r"(b[0]), "r"(b[1]));
}

template<bool TB>
__global__ void __launch_bounds__(256, 2)
gemm_tc(const float* __restrict__ A, const float* __restrict__ B,
        float* __restrict__ C,
        int M, int N, int K,
        size_t sA, size_t sB, size_t sC,
        float alpha,
        const float* __restrict__ bias,
        const float* __restrict__ addend,
        int do_gelu)
{
    extern __shared__ float smem[];
    float* As = smem;
    float* Bs = smem + STAGES * A_STAGE_FLTS;

    const int t    = threadIdx.x;
    const int lane = t & 31;
    const int wid  = t >> 5;
    const int warpM = wid & 1;   // 0..1 -> 64 rows each
    const int warpN = wid >> 1;  // 0..3 -> 32 cols each
    const int mBase = warpM * 64;
    const int nBase = warpN * 32;
    const int grp   = lane >> 2;   // 0..7
    const int tig   = lane & 3;    // 0..3

    const int m0 = blockIdx.y * 128;
    const int n0 = blockIdx.x * 128;
    const float* Ab = A + (size_t)blockIdx.z * sA;
    const float* Bp = B + (size_t)blockIdx.z * sB;
    float*       Cb = C + (size_t)blockIdx.z * sC;

    float acc[4][4][4];
    #pragma unroll
    for (int i = 0; i < 4; ++i)
        #pragma unroll
        for (int j = 0; j < 4; ++j)
            #pragma unroll
            for (int r = 0; r < 4; ++r) acc[i][j][r] = 0.f;

    const int nk = K >> 4;

    // ---- tile loader: stage s <- k-tile kt ----
    auto load_tile = [&](int kt, int s) {
        const int kb = kt << 4;
        float* Ad = As + s * A_STAGE_FLTS;
        #pragma unroll
        for (int l = 0; l < 2; ++l) {
            int idx = t + l * 256;
            int m = idx >> 2, kc = (idx & 3) << 2;
            cp_async16(Ad + m * ASTR + kc, Ab + (size_t)(m0 + m) * K + kb + kc);
        }
        float* Bd = Bs + s * B_STAGE_FLTS;
        if (TB) {
            #pragma unroll
            for (int l = 0; l < 2; ++l) {
                int idx = t + l * 256;
                int n = idx >> 2, kc = (idx & 3) << 2;
                cp_async16(Bd + n * ASTR + kc, Bp + (size_t)(n0 + n) * K + kb + kc);
            }
        } else {
            #pragma unroll
            for (int l = 0; l < 2; ++l) {
                int idx = t + l * 256;
                int kr = idx >> 5, nc = (idx & 31) << 2;
                cp_async16(Bd + kr * BSTR_NN + nc, Bp + (size_t)(kb + kr) * N + n0 + nc);
            }
        }
    };

    // prologue
    #pragma unroll
    for (int i = 0; i < STAGES - 1; ++i) {
        if (i < nk) load_tile(i, i);
        cp_commit();
    }

    for (int kt = 0; kt < nk; ++kt) {
        cp_wait<STAGES - 2>();
        __syncthreads();

        const int s = kt % STAGES;
        const float* Asb = As + s * A_STAGE_FLTS;
        const float* Bsb = Bs + s * B_STAGE_FLTS;

        #pragma unroll
        for (int s8 = 0; s8 < 2; ++s8) {
            const int kk = s8 * 8;
            unsigned af[4][4], bf[4][2];
            #pragma unroll
            for (int mt = 0; mt < 4; ++mt) {
                int r = mBase + mt * 16 + grp;
                af[mt][0] = f2tf32(Asb[(size_t)r * ASTR + kk + tig]);
                af[mt][1] = f2tf32(Asb[(size_t)(r + 8) * ASTR + kk + tig]);
                af[mt][2] = f2tf32(Asb[(size_t)r * ASTR + kk + tig + 4]);
                af[mt][3] = f2tf32(Asb[(size_t)(r + 8) * ASTR + kk + tig + 4]);
            }
            if (TB) {
                #pragma unroll
                for (int nt = 0; nt < 4; ++nt) {
                    int n = nBase + nt * 8 + grp;
                    bf[nt][0] = f2tf32(Bsb[(size_t)n * ASTR + kk + tig]);
                    bf[nt][1] = f2tf32(Bsb[(size_t)n * ASTR + kk + tig + 4]);
                }
            } else {
                #pragma unroll
                for (int nt = 0; nt < 4; ++nt) {
                    int n = nBase + nt * 8 + grp;
                    bf[nt][0] = f2tf32(Bsb[(size_t)(kk + tig) * BSTR_NN + n]);
                    bf[nt][1] = f2tf32(Bsb[(size_t)(kk + tig + 4) * BSTR_NN + n]);
                }
            }
            #pragma unroll
            for (int mt = 0; mt < 4; ++mt)
                #pragma unroll
                for (int nt = 0; nt < 4; ++nt)
                    mma_tf32(acc[mt][nt], af[mt], bf[nt]);
        }
        __syncthreads();

        const int ktn = kt + STAGES - 1;
        if (ktn < nk) load_tile(ktn, ktn % STAGES);
        cp_commit();
    }

    // ---- epilogue: alpha -> +bias -> gelu -> +addend -> store ----
    #pragma unroll
    for (int mt = 0; mt < 4; ++mt) {
        int r0 = m0 + mBase + mt * 16 + grp;
        #pragma unroll
        for (int nt = 0; nt < 4; ++nt) {
            int c0 = n0 + nBase + nt * 8 + 2 * tig;
            float v00 = acc[mt][nt][0] * alpha;
            float v01 = acc[mt][nt][1] * alpha;
            float v10 = acc[mt][nt][2] * alpha;
            float v11 = acc[mt][nt][3] * alpha;
            if (bias) {
                float bv0 = bias[c0], bv1 = bias[c0 + 1];
                v00 += bv0; v01 += bv1; v10 += bv0; v11 += bv1;
            }
            if (do_gelu) {
                v00 = 0.5f * v00 * (1.0f + erff(v00 * 0.7071067811865475f));
                v01 = 0.5f * v01 * (1.0f + erff(v01 * 0.7071067811865475f));
                v10 = 0.5f * v10 * (1.0f + erff(v10 * 0.7071067811865475f));
                v11 = 0.5f * v11 * (1.0f + erff(v11 * 0.7071067811865475f));
            }
            if (addend) {
                const float* Ad = addend + (size_t)blockIdx.z * sC;
                v00 += Ad[(size_t)r0 * N + c0];
                v01 += Ad[(size_t)r0 * N + c0 + 1];
                v10 += Ad[(size_t)(r0 + 8) * N + c0];
                v11 += Ad[(size_t)(r0 + 8) * N + c0 + 1];
            }
            Cb[(size_t)r0 * N + c0]           = v00;
            Cb[(size_t)r0 * N + c0 + 1]       = v01;
            Cb[(size_t)(r0 + 8) * N + c0]     = v10;
            Cb[(size_t)(r0 + 8) * N + c0 + 1] = v11;
        }
    }
}

// ---------------- launch ----------------
extern "C" void kernel_launch(void* const* d_in, const int* in_sizes, int n_in,
                              void* d_out, int out_size)
{
    const float* q      = (const float*)d_in[0];
    const float* k      = (const float*)d_in[1];
    const float* v      = (const float*)d_in[2];
    const float* W_diff = (const float*)d_in[3];
    const float* b_diff = (const float*)d_in[4];
    const float* ln_g   = (const float*)d_in[5];
    const float* ln_b   = (const float*)d_in[6];
    const float* W1     = (const float*)d_in[7];
    const float* b1     = (const float*)d_in[8];
    const float* W2     = (const float*)d_in[9];
    const float* b2     = (const float*)d_in[10];
    float* out = (float*)d_out;

    float *pX, *pL, *pAttn, *pAf, *pFd, *pH, *pAct, *pOut;
    cudaGetSymbolAddress((void**)&pX,    g_X);
    cudaGetSymbolAddress((void**)&pL,    g_L);
    cudaGetSymbolAddress((void**)&pAttn, g_attn);
    cudaGetSymbolAddress((void**)&pAf,   g_af);
    cudaGetSymbolAddress((void**)&pFd,   g_fd);
    cudaGetSymbolAddress((void**)&pH,    g_h);
    cudaGetSymbolAddress((void**)&pAct,  g_act);
    cudaGetSymbolAddress((void**)&pOut,  g_out);

    cudaFuncSetAttribute(gemm_tc<true>,  cudaFuncAttributeMaxDynamicSharedMemorySize, SMEM_BYTES);
    cudaFuncSetAttribute(gemm_tc<false>, cudaFuncAttributeMaxDynamicSharedMemorySize, SMEM_BYTES);

    const size_t sND = (size_t)NN_ * DD;
    const size_t sNN = (size_t)NN_ * NN_;

    // 1) q_prob/k_prob -> X, L
    prob_kernel<<<BN, 256>>>(q, k, pX, pL);

    // 2) sid logits: attn = -(X @ L^T) / 32   (batched NT)
    gemm_tc<true><<<dim3(NN_ / 128, NN_ / 128, BB), 256, SMEM_BYTES>>>(
        pX, pL, pAttn, NN_, NN_, DD, sND, sND, sNN,
        -1.0f / 32.0f, nullptr, nullptr, 0);

    // 3) softmax rows (in place)
    softmax_kernel<<<BN, 512>>>(pAttn);

    // 4) attn_feat = attn @ v   (batched NN)
    gemm_tc<false><<<dim3(DD / 128, NN_ / 128, BB), 256, SMEM_BYTES>>>(
        pAttn, v, pAf, NN_, DD, NN_, sNN, sND, sND,
        1.0f, nullptr, nullptr, 0);

    // 5) vd = v - attn_feat  (reuse g_X)
    {
        size_t n4 = (size_t)BN * DD / 4;
        sub_kernel<<<(unsigned)((n4 + 255) / 256), 256>>>(v, pAf, pX, n4);
    }

    // 6) f_diff = vd @ W_diff^T + b_diff + q
    gemm_tc<true><<<dim3(DD / 128, BN / 128, 1), 256, SMEM_BYTES>>>(
        pX, W_diff, pFd, BN, DD, DD, 0, 0, 0,
        1.0f, b_diff, q, 0);

    // 7) h = LN(f_diff)
    layernorm_kernel<<<BN, 256>>>(pFd, ln_g, ln_b, pH);

    // 8) act = gelu(h @ W1^T + b1)
    gemm_tc<true><<<dim3(HH / 128, BN / 128, 1), 256, SMEM_BYTES>>>(
        pH, W1, pAct, BN, HH, DD, 0, 0, 0,
        1.0f, b1, nullptr, 1);

    // 9) out_pre = act @ W2^T + b2 + f_diff
    gemm_tc<true><<<dim3(DD / 128, BN / 128, 1), 256, SMEM_BYTES>>>(
        pAct, W2, pOut, BN, DD, HH, 0, 0, 0,
        1.0f, b2, pFd, 0);

    // 10) final LN -> d_out
    layernorm_kernel<<<BN, 256>>>(pOut, ln_g, ln_b, out);
}

// round 3
// speedup vs baseline: 2.9004x; 1.0052x over previous
#include <cuda_runtime.h>
#include <math.h>

// Problem dims (fixed per setup_inputs)
#define BB 8
#define NN_ 2048
#define DD 1024
#define HH 4096
#define BN (BB * NN_)   // 16384

// ---------------- scratch (static device globals; no allocation) ----------------
__device__ __align__(256) float g_X   [(size_t)BN * DD];      // X = qp - kp (rounded); reused for vd
__device__ __align__(256) float g_L   [(size_t)BN * DD];      // log-ratio (rounded); reused for v_rounded
__device__ __align__(256) float g_attn[(size_t)BB * NN_ * NN_];
__device__ __align__(256) float g_af  [(size_t)BN * DD];
__device__ __align__(256) float g_fd  [(size_t)BN * DD];
__device__ __align__(256) float g_h   [(size_t)BN * DD];
__device__ __align__(256) float g_act [(size_t)BN * HH];
__device__ __align__(256) float g_out [(size_t)BN * DD];
__device__ __align__(256) float g_wdr [(size_t)DD * DD];      // rounded W_diff
__device__ __align__(256) float g_w1r [(size_t)HH * DD];      // rounded W1
__device__ __align__(256) float g_w2r [(size_t)HH * DD];      // rounded W2

// ---------------- tf32 rounding helper ----------------
__device__ __forceinline__ float tf32r(float x) {
    unsigned r; asm("cvt.rna.tf32.f32 %0, %1;" : "=r"(r) : "f"(x));
    return __uint_as_float(r);
}

// ---------------- reductions ----------------
__device__ __forceinline__ float block_sum_256(float v, float* sbuf) {
    #pragma unroll
    for (int o = 16; o; o >>= 1) v += __shfl_xor_sync(0xffffffffu, v, o);
    int w = threadIdx.x >> 5;
    if ((threadIdx.x & 31) == 0) sbuf[w] = v;
    __syncthreads();
    if (threadIdx.x < 8) {
        v = sbuf[threadIdx.x];
        #pragma unroll
        for (int o = 4; o; o >>= 1) v += __shfl_xor_sync(0xffu, v, o);
        if (threadIdx.x == 0) sbuf[0] = v;
    }
    __syncthreads();
    float r = sbuf[0];
    __syncthreads();
    return r;
}

// ---------------- prob / log-ratio kernel (outputs tf32-rounded) ----------------
__global__ void __launch_bounds__(256)
prob_kernel(const float* __restrict__ q, const float* __restrict__ k,
            float* __restrict__ X, float* __restrict__ L)
{
    __shared__ float sbuf[8];
    size_t base = (size_t)blockIdx.x * DD;
    int t = threadIdx.x;
    float tq[4], tk[4];
    float sq = 0.f, sk = 0.f;
    #pragma unroll
    for (int l = 0; l < 4; ++l) {
        int i = t + l * 256;
        tq[l] = tanhf(q[base + i]) * 0.499f + 0.5f;
        tk[l] = tanhf(k[base + i]) * 0.499f + 0.5f;
        sq += tq[l]; sk += tk[l];
    }
    float sumq = block_sum_256(sq, sbuf);
    float sumk = block_sum_256(sk, sbuf);
    float iq = 1.f / (sumq + 1e-8f);
    float ik = 1.f / (sumk + 1e-8f);
    #pragma unroll
    for (int l = 0; l < 4; ++l) {
        int i = t + l * 256;
        float pq = fmaxf(tq[l] * iq, 1e-8f);
        float pk = fmaxf(tk[l] * ik, 1e-8f);
        X[base + i] = tf32r(pq - pk);
        L[base + i] = tf32r(logf(pq) - logf(pk));
    }
}

// ---------------- softmax over last dim (row length 2048), in place, rounded ----------------
__global__ void __launch_bounds__(512)
softmax_kernel(float* __restrict__ A)
{
    __shared__ float sbuf[16];
    size_t base = (size_t)blockIdx.x * NN_;
    int t = threadIdx.x;
    float x[4];
    float mx = -1e30f;
    #pragma unroll
    for (int l = 0; l < 4; ++l) { x[l] = A[base + t + l * 512]; mx = fmaxf(mx, x[l]); }
    #pragma unroll
    for (int o = 16; o; o >>= 1) mx = fmaxf(mx, __shfl_xor_sync(0xffffffffu, mx, o));
    int w = t >> 5;
    if ((t & 31) == 0) sbuf[w] = mx;
    __syncthreads();
    if (t < 16) {
        mx = sbuf[t];
        #pragma unroll
        for (int o = 8; o; o >>= 1) mx = fmaxf(mx, __shfl_xor_sync(0xffffu, mx, o));
        if (t == 0) sbuf[0] = mx;
    }
    __syncthreads();
    mx = sbuf[0];
    __syncthreads();

    float s = 0.f;
    #pragma unroll
    for (int l = 0; l < 4; ++l) { x[l] = expf(x[l] - mx); s += x[l]; }
    #pragma unroll
    for (int o = 16; o; o >>= 1) s += __shfl_xor_sync(0xffffffffu, s, o);
    if ((t & 31) == 0) sbuf[w] = s;
    __syncthreads();
    if (t < 16) {
        s = sbuf[t];
        #pragma unroll
        for (int o = 8; o; o >>= 1) s += __shfl_xor_sync(0xffffu, s, o);
        if (t == 0) sbuf[0] = s;
    }
    __syncthreads();
    float inv = 1.f / sbuf[0];
    #pragma unroll
    for (int l = 0; l < 4; ++l) A[base + t + l * 512] = tf32r(x[l] * inv);
}

// ---------------- layernorm (row length 1024); optional tf32 rounding ----------------
__global__ void __launch_bounds__(256)
layernorm_kernel(const float* __restrict__ in, const float* __restrict__ g,
                 const float* __restrict__ b, float* __restrict__ out, int do_round)
{
    __shared__ float sbuf[8];
    size_t base = (size_t)blockIdx.x * DD;
    int t = threadIdx.x;
    float x[4]; float s = 0.f;
    #pragma unroll
    for (int l = 0; l < 4; ++l) { x[l] = in[base + t + l * 256]; s += x[l]; }
    float mean = block_sum_256(s, sbuf) * (1.f / DD);
    float vs = 0.f;
    #pragma unroll
    for (int l = 0; l < 4; ++l) { float d = x[l] - mean; vs += d * d; }
    float var = block_sum_256(vs, sbuf) * (1.f / DD);
    float r = rsqrtf(var + 1e-5f);
    #pragma unroll
    for (int l = 0; l < 4; ++l) {
        int i = t + l * 256;
        float o = (x[l] - mean) * r * g[i] + b[i];
        out[base + i] = do_round ? tf32r(o) : o;
    }
}

// ---------------- elementwise c = round(a - b) (float4) ----------------
__global__ void __launch_bounds__(256)
sub_kernel(const float* __restrict__ a, const float* __restrict__ b,
           float* __restrict__ c, size_t n4)
{
    size_t i = (size_t)blockIdx.x * blockDim.x + threadIdx.x;
    if (i < n4) {
        float4 va = ((const float4*)a)[i];
        float4 vb = ((const float4*)b)[i];
        ((float4*)c)[i] = make_float4(tf32r(va.x - vb.x), tf32r(va.y - vb.y),
                                      tf32r(va.z - vb.z), tf32r(va.w - vb.w));
    }
}

// ---------------- elementwise tf32 round copy ----------------
__global__ void __launch_bounds__(256)
round_kernel(const float* __restrict__ src, float* __restrict__ dst, size_t n4)
{
    size_t i = (size_t)blockIdx.x * blockDim.x + threadIdx.x;
    if (i < n4) {
        float4 v = ((const float4*)src)[i];
        ((float4*)dst)[i] = make_float4(tf32r(v.x), tf32r(v.y), tf32r(v.z), tf32r(v.w));
    }
}

// ---------------- tf32 tensor-core GEMM (operands pre-rounded; no cvt in loop) ----------------
// C[m,n] = alpha * sum_k A[m,k] * (TB ? B[n,k] : B[k,n])  (+bias[n]) (gelu+round) (+addend[m,n])
// 128x128 block tile, kTile=16, 4-stage cp.async pipeline, 8 warps (2x4),
// warp tile 64x32 via mma.sync.m16n8k8.tf32.

#define STAGES 4
#define ASTR 20          // smem stride for [row][k] layouts
#define BSTR_NN 136      // smem stride for [k][n] layout
#define A_STAGE_FLTS (128 * ASTR)       // 2560
#define B_STAGE_FLTS (128 * ASTR)       // 2560
#define SMEM_FLTS (STAGES * (A_STAGE_FLTS + B_STAGE_FLTS))
#define SMEM_BYTES (SMEM_FLTS * 4)      // 81920

__device__ __forceinline__ void cp_async16(void* s, const void* g) {
    unsigned sa = (unsigned)__cvta_generic_to_shared(s);
    asm volatile("cp.async.cg.shared.global [%0], [%1], 16;\n" :: "r"(sa), "l"(g));
}
__device__ __forceinline__ void cp_commit() { asm volatile("cp.async.commit_group;\n" ::: "memory"); }
template<int NW> __device__ __forceinline__ void cp_wait() {
    asm volatile("cp.async.wait_group %0;\n" :: "n"(NW) : "memory");
}
__device__ __forceinline__ void mma_tf32(float c[4], const unsigned a[4], const unsigned b[2]) {
    asm volatile(
        "mma.sync.aligned.m16n8k8.row.col.f32.tf32.tf32.f32 "
        "{%0,%1,%2,%3}, {%4,%5,%6,%7}, {%8,%9}, {%0,%1,%2,%3};"
        : "+f"(c[0]), "+f"(c[1]), "+f"(c[2]), "+f"(c[3])
        : "r"(a[0]), "r"(a[1]), "r"(a[2]), "r"(a[3]), "r"(b[0]), "r"(b[1]));
}

template<bool TB>
__global__ void __launch_bounds__(256, 2)
gemm_tc(const float* __restrict__ A, const float* __restrict__ B,
        float* __restrict__ C,
        int M, int N, int K,
        size_t sA, size_t sB, size_t sC,
        float alpha,
        const float* __restrict__ bias,
        const float* __restrict__ addend,
        int do_gelu)
{
    extern __shared__ float smem[];
    float* As = smem;
    float* Bs = smem + STAGES * A_STAGE_FLTS;

    const int t    = threadIdx.x;
    const int lane = t & 31;
    const int wid  = t >> 5;
    const int mBase = (wid & 1) * 64;
    const int nBase = (wid >> 1) * 32;
    const int grp   = lane >> 2;   // 0..7
    const int tig   = lane & 3;    // 0..3

    const int m0 = blockIdx.y * 128;
    const int n0 = blockIdx.x * 128;
    const float* Ab = A + (size_t)blockIdx.z * sA;
    const float* Bp = B + (size_t)blockIdx.z * sB;
    float*       Cb = C + (size_t)blockIdx.z * sC;

    float acc[4][4][4];
    #pragma unroll
    for (int i = 0; i < 4; ++i)
        #pragma unroll
        for (int j = 0; j < 4; ++j)
            #pragma unroll
            for (int r = 0; r < 4; ++r) acc[i][j][r] = 0.f;

    const int nk = K >> 4;

    auto load_tile = [&](int kt, int s) {
        const int kb = kt << 4;
        float* Ad = As + s * A_STAGE_FLTS;
        #pragma unroll
        for (int l = 0; l < 2; ++l) {
            int idx = t + l * 256;
            int m = idx >> 2, kc = (idx & 3) << 2;
            cp_async16(Ad + m * ASTR + kc, Ab + (size_t)(m0 + m) * K + kb + kc);
        }
        float* Bd = Bs + s * B_STAGE_FLTS;
        if (TB) {
            #pragma unroll
            for (int l = 0; l < 2; ++l) {
                int idx = t + l * 256;
                int n = idx >> 2, kc = (idx & 3) << 2;
                cp_async16(Bd + n * ASTR + kc, Bp + (size_t)(n0 + n) * K + kb + kc);
            }
        } else {
            #pragma unroll
            for (int l = 0; l < 2; ++l) {
                int idx = t + l * 256;
                int kr = idx >> 5, nc = (idx & 31) << 2;
                cp_async16(Bd + kr * BSTR_NN + nc, Bp + (size_t)(kb + kr) * N + n0 + nc);
            }
        }
    };

    // prologue: fill stages 0..STAGES-2
    #pragma unroll
    for (int i = 0; i < STAGES - 1; ++i) {
        if (i < nk) load_tile(i, i);
        cp_commit();
    }

    for (int kt = 0; kt < nk; ++kt) {
        // issue next tile load at loop top (target stage was freed last iteration)
        const int ktn = kt + STAGES - 1;
        if (ktn < nk) load_tile(ktn, ktn % STAGES);
        cp_commit();

        cp_wait<STAGES - 2>();
        __syncthreads();

        const int s = kt % STAGES;
        const float* Asb = As + s * A_STAGE_FLTS;
        const float* Bsb = Bs + s * B_STAGE_FLTS;

        #pragma unroll
        for (int s8 = 0; s8 < 2; ++s8) {
            const int kk = s8 * 8;
            unsigned af[4][4], bf[4][2];
            #pragma unroll
            for (int mt = 0; mt < 4; ++mt) {
                int r = mBase + mt * 16 + grp;
                af[mt][0] = __float_as_uint(Asb[r * ASTR + kk + tig]);
                af[mt][1] = __float_as_uint(Asb[(r + 8) * ASTR + kk + tig]);
                af[mt][2] = __float_as_uint(Asb[r * ASTR + kk + tig + 4]);
                af[mt][3] = __float_as_uint(Asb[(r + 8) * ASTR + kk + tig + 4]);
            }
            if (TB) {
                #pragma unroll
                for (int nt = 0; nt < 4; ++nt) {
                    int n = nBase + nt * 8 + grp;
                    bf[nt][0] = __float_as_uint(Bsb[n * ASTR + kk + tig]);
                    bf[nt][1] = __float_as_uint(Bsb[n * ASTR + kk + tig + 4]);
                }
            } else {
                #pragma unroll
                for (int nt = 0; nt < 4; ++nt) {
                    int n = nBase + nt * 8 + grp;
                    bf[nt][0] = __float_as_uint(Bsb[(kk + tig) * BSTR_NN + n]);
                    bf[nt][1] = __float_as_uint(Bsb[(kk + tig + 4) * BSTR_NN + n]);
                }
            }
            #pragma unroll
            for (int mt = 0; mt < 4; ++mt)
                #pragma unroll
                for (int nt = 0; nt < 4; ++nt)
                    mma_tf32(acc[mt][nt], af[mt], bf[nt]);
        }
        __syncthreads();
    }

    // ---- epilogue: alpha -> +bias -> gelu(+round) -> +addend -> store ----
    #pragma unroll
    for (int mt = 0; mt < 4; ++mt) {
        int r0 = m0 + mBase + mt * 16 + grp;
        #pragma unroll
        for (int nt = 0; nt < 4; ++nt) {
            int c0 = n0 + nBase + nt * 8 + 2 * tig;
            float v00 = acc[mt][nt][0] * alpha;
            float v01 = acc[mt][nt][1] * alpha;
            float v10 = acc[mt][nt][2] * alpha;
            float v11 = acc[mt][nt][3] * alpha;
            if (bias) {
                float bv0 = bias[c0], bv1 = bias[c0 + 1];
                v00 += bv0; v01 += bv1; v10 += bv0; v11 += bv1;
            }
            if (do_gelu) {
                v00 = tf32r(0.5f * v00 * (1.0f + erff(v00 * 0.7071067811865475f)));
                v01 = tf32r(0.5f * v01 * (1.0f + erff(v01 * 0.7071067811865475f)));
                v10 = tf32r(0.5f * v10 * (1.0f + erff(v10 * 0.7071067811865475f)));
                v11 = tf32r(0.5f * v11 * (1.0f + erff(v11 * 0.7071067811865475f)));
            }
            if (addend) {
                const float* Ad = addend + (size_t)blockIdx.z * sC;
                v00 += Ad[(size_t)r0 * N + c0];
                v01 += Ad[(size_t)r0 * N + c0 + 1];
                v10 += Ad[(size_t)(r0 + 8) * N + c0];
                v11 += Ad[(size_t)(r0 + 8) * N + c0 + 1];
            }
            Cb[(size_t)r0 * N + c0]           = v00;
            Cb[(size_t)r0 * N + c0 + 1]       = v01;
            Cb[(size_t)(r0 + 8) * N + c0]     = v10;
            Cb[(size_t)(r0 + 8) * N + c0 + 1] = v11;
        }
    }
}

// ---------------- launch ----------------
extern "C" void kernel_launch(void* const* d_in, const int* in_sizes, int n_in,
                              void* d_out, int out_size)
{
    const float* q      = (const float*)d_in[0];
    const float* k      = (const float*)d_in[1];
    const float* v      = (const float*)d_in[2];
    const float* W_diff = (const float*)d_in[3];
    const float* b_diff = (const float*)d_in[4];
    const float* ln_g   = (const float*)d_in[5];
    const float* ln_b   = (const float*)d_in[6];
    const float* W1     = (const float*)d_in[7];
    const float* b1     = (const float*)d_in[8];
    const float* W2     = (const float*)d_in[9];
    const float* b2     = (const float*)d_in[10];
    float* out = (float*)d_out;

    float *pX, *pL, *pAttn, *pAf, *pFd, *pH, *pAct, *pOut, *pWd, *pW1, *pW2;
    cudaGetSymbolAddress((void**)&pX,    g_X);
    cudaGetSymbolAddress((void**)&pL,    g_L);
    cudaGetSymbolAddress((void**)&pAttn, g_attn);
    cudaGetSymbolAddress((void**)&pAf,   g_af);
    cudaGetSymbolAddress((void**)&pFd,   g_fd);
    cudaGetSymbolAddress((void**)&pH,    g_h);
    cudaGetSymbolAddress((void**)&pAct,  g_act);
    cudaGetSymbolAddress((void**)&pOut,  g_out);
    cudaGetSymbolAddress((void**)&pWd,   g_wdr);
    cudaGetSymbolAddress((void**)&pW1,   g_w1r);
    cudaGetSymbolAddress((void**)&pW2,   g_w2r);

    cudaFuncSetAttribute(gemm_tc<true>,  cudaFuncAttributeMaxDynamicSharedMemorySize, SMEM_BYTES);
    cudaFuncSetAttribute(gemm_tc<false>, cudaFuncAttributeMaxDynamicSharedMemorySize, SMEM_BYTES);

    const size_t sND = (size_t)NN_ * DD;
    const size_t sNN = (size_t)NN_ * NN_;

    // 0) round weights into scratch (tiny)
    round_kernel<<<(DD * DD / 4 + 255) / 256, 256>>>(W_diff, pWd, (size_t)DD * DD / 4);
    round_kernel<<<((size_t)HH * DD / 4 + 255) / 256, 256>>>(W1, pW1, (size_t)HH * DD / 4);
    round_kernel<<<((size_t)HH * DD / 4 + 255) / 256, 256>>>(W2, pW2, (size_t)HH * DD / 4);

    // 1) q_prob/k_prob -> X, L (rounded)
    prob_kernel<<<BN, 256>>>(q, k, pX, pL);

    // 2) sid logits: attn = -(X @ L^T) / 32   (batched NT)
    gemm_tc<true><<<dim3(NN_ / 128, NN_ / 128, BB), 256, SMEM_BYTES>>>(
        pX, pL, pAttn, NN_, NN_, DD, sND, sND, sNN,
        -1.0f / 32.0f, nullptr, nullptr, 0);

    // 2b) rounded copy of v into g_L (g_L is dead after sid GEMM)
    round_kernel<<<(unsigned)(((size_t)BN * DD / 4 + 255) / 256), 256>>>(v, pL, (size_t)BN * DD / 4);

    // 3) softmax rows (in place, rounded)
    softmax_kernel<<<BN, 512>>>(pAttn);

    // 4) attn_feat = attn @ v_rounded   (batched NN)
    gemm_tc<false><<<dim3(DD / 128, NN_ / 128, BB), 256, SMEM_BYTES>>>(
        pAttn, pL, pAf, NN_, DD, NN_, sNN, sND, sND,
        1.0f, nullptr, nullptr, 0);

    // 5) vd = round(v - attn_feat)  (reuse g_X; original v for exact subtraction)
    {
        size_t n4 = (size_t)BN * DD / 4;
        sub_kernel<<<(unsigned)((n4 + 255) / 256), 256>>>(v, pAf, pX, n4);
    }

    // 6) f_diff = vd @ W_diff^T + b_diff + q
    gemm_tc<true><<<dim3(DD / 128, BN / 128, 1), 256, SMEM_BYTES>>>(
        pX, pWd, pFd, BN, DD, DD, 0, 0, 0,
        1.0f, b_diff, q, 0);

    // 7) h = LN(f_diff), rounded (GEMM operand)
    layernorm_kernel<<<BN, 256>>>(pFd, ln_g, ln_b, pH, 1);

    // 8) act = round(gelu(h @ W1^T + b1))
    gemm_tc<true><<<dim3(HH / 128, BN / 128, 1), 256, SMEM_BYTES>>>(
        pH, pW1, pAct, BN, HH, DD, 0, 0, 0,
        1.0f, b1, nullptr, 1);

    // 9) out_pre = act @ W2^T + b2 + f_diff
    gemm_tc<true><<<dim3(DD / 128, BN / 128, 1), 256, SMEM_BYTES>>>(
        pAct, pW2, pOut, BN, DD, HH, 0, 0, 0,
        1.0f, b2, pFd, 0);

    // 10) final LN -> d_out (no rounding)
    layernorm_kernel<<<BN, 256>>>(pOut, ln_g, ln_b, out, 0);
}

// round 4
// speedup vs baseline: 5.1336x; 1.7700x over previous
#include <cuda_runtime.h>
#include <cuda_fp16.h>
#include <math.h>

// Problem dims (fixed per setup_inputs)
#define BB 8
#define NN_ 2048
#define DD 1024
#define HH 4096
#define BN (BB * NN_)   // 16384

// ---------------- scratch (static device globals; no allocation) ----------------
// fp32
__device__ __align__(256) float  g_attn [(size_t)BB * NN_ * NN_];  // sid logits (f32)
__device__ __align__(256) float  g_af   [(size_t)BN * DD];
__device__ __align__(256) float  g_fd   [(size_t)BN * DD];
__device__ __align__(256) float  g_out  [(size_t)BN * DD];
// fp16 operands
__device__ __align__(256) __half g_hX   [(size_t)BN * DD];   // (qp-kp)*1024
__device__ __align__(256) __half g_hL   [(size_t)BN * DD];   // log ratio
__device__ __align__(256) __half g_hVt  [(size_t)BN * DD];   // v transposed per batch [d][token]
__device__ __align__(256) __half g_attnh[(size_t)BB * NN_ * NN_];
__device__ __align__(256) __half g_hVd  [(size_t)BN * DD];   // v - attn_feat
__device__ __align__(256) __half g_hH   [(size_t)BN * DD];   // LN(f_diff)
__device__ __align__(256) __half g_hAct [(size_t)BN * HH];   // gelu(mlp1)
__device__ __align__(256) __half g_hWd  [(size_t)DD * DD];
__device__ __align__(256) __half g_hW1  [(size_t)HH * DD];
__device__ __align__(256) __half g_hW2  [(size_t)HH * DD];

// ---------------- reductions ----------------
__device__ __forceinline__ float block_sum_256(float v, float* sbuf) {
    #pragma unroll
    for (int o = 16; o; o >>= 1) v += __shfl_xor_sync(0xffffffffu, v, o);
    int w = threadIdx.x >> 5;
    if ((threadIdx.x & 31) == 0) sbuf[w] = v;
    __syncthreads();
    if (threadIdx.x < 8) {
        v = sbuf[threadIdx.x];
        #pragma unroll
        for (int o = 4; o; o >>= 1) v += __shfl_xor_sync(0xffu, v, o);
        if (threadIdx.x == 0) sbuf[0] = v;
    }
    __syncthreads();
    float r = sbuf[0];
    __syncthreads();
    return r;
}

// ---------------- prob / log-ratio kernel -> fp16 (X scaled by 1024) ----------------
__global__ void __launch_bounds__(256)
prob_kernel(const float* __restrict__ q, const float* __restrict__ k,
            __half* __restrict__ X, __half* __restrict__ L)
{
    __shared__ float sbuf[8];
    size_t base = (size_t)blockIdx.x * DD;
    int t = threadIdx.x;
    float tq[4], tk[4];
    float sq = 0.f, sk = 0.f;
    #pragma unroll
    for (int l = 0; l < 4; ++l) {
        int i = t + l * 256;
        tq[l] = tanhf(q[base + i]) * 0.499f + 0.5f;
        tk[l] = tanhf(k[base + i]) * 0.499f + 0.5f;
        sq += tq[l]; sk += tk[l];
    }
    float sumq = block_sum_256(sq, sbuf);
    float sumk = block_sum_256(sk, sbuf);
    float iq = 1.f / (sumq + 1e-8f);
    float ik = 1.f / (sumk + 1e-8f);
    #pragma unroll
    for (int l = 0; l < 4; ++l) {
        int i = t + l * 256;
        float pq = fmaxf(tq[l] * iq, 1e-8f);
        float pk = fmaxf(tk[l] * ik, 1e-8f);
        X[base + i] = __float2half_rn((pq - pk) * 1024.0f);
        L[base + i] = __float2half_rn(logf(pq) - logf(pk));
    }
}

// ---------------- softmax over last dim (2048): f32 in, fp16 out ----------------
__global__ void __launch_bounds__(512)
softmax_kernel(const float* __restrict__ A, __half* __restrict__ O)
{
    __shared__ float sbuf[16];
    size_t base = (size_t)blockIdx.x * NN_;
    int t = threadIdx.x;
    float x[4];
    float mx = -1e30f;
    #pragma unroll
    for (int l = 0; l < 4; ++l) { x[l] = A[base + t + l * 512]; mx = fmaxf(mx, x[l]); }
    #pragma unroll
    for (int o = 16; o; o >>= 1) mx = fmaxf(mx, __shfl_xor_sync(0xffffffffu, mx, o));
    int w = t >> 5;
    if ((t & 31) == 0) sbuf[w] = mx;
    __syncthreads();
    if (t < 16) {
        mx = sbuf[t];
        #pragma unroll
        for (int o = 8; o; o >>= 1) mx = fmaxf(mx, __shfl_xor_sync(0xffffu, mx, o));
        if (t == 0) sbuf[0] = mx;
    }
    __syncthreads();
    mx = sbuf[0];
    __syncthreads();

    float s = 0.f;
    #pragma unroll
    for (int l = 0; l < 4; ++l) { x[l] = expf(x[l] - mx); s += x[l]; }
    #pragma unroll
    for (int o = 16; o; o >>= 1) s += __shfl_xor_sync(0xffffffffu, s, o);
    if ((t & 31) == 0) sbuf[w] = s;
    __syncthreads();
    if (t < 16) {
        s = sbuf[t];
        #pragma unroll
        for (int o = 8; o; o >>= 1) s += __shfl_xor_sync(0xffffu, s, o);
        if (t == 0) sbuf[0] = s;
    }
    __syncthreads();
    float inv = 1.f / sbuf[0];
    #pragma unroll
    for (int l = 0; l < 4; ++l) O[base + t + l * 512] = __float2half_rn(x[l] * inv);
}

// ---------------- layernorm (row 1024); out fp32 or fp16 ----------------
__global__ void __launch_bounds__(256)
layernorm_kernel(const float* __restrict__ in, const float* __restrict__ g,
                 const float* __restrict__ b, void* __restrict__ outp, int out_half)
{
    __shared__ float sbuf[8];
    size_t base = (size_t)blockIdx.x * DD;
    int t = threadIdx.x;
    float x[4]; float s = 0.f;
    #pragma unroll
    for (int l = 0; l < 4; ++l) { x[l] = in[base + t + l * 256]; s += x[l]; }
    float mean = block_sum_256(s, sbuf) * (1.f / DD);
    float vs = 0.f;
    #pragma unroll
    for (int l = 0; l < 4; ++l) { float d = x[l] - mean; vs += d * d; }
    float var = block_sum_256(vs, sbuf) * (1.f / DD);
    float r = rsqrtf(var + 1e-5f);
    #pragma unroll
    for (int l = 0; l < 4; ++l) {
        int i = t + l * 256;
        float o = (x[l] - mean) * r * g[i] + b[i];
        if (out_half) ((__half*)outp)[base + i] = __float2half_rn(o);
        else          ((float*)outp)[base + i] = o;
    }
}

// ---------------- vd = half(a - b) ----------------
__global__ void __launch_bounds__(256)
sub_h_kernel(const float* __restrict__ a, const float* __restrict__ b,
             __half* __restrict__ c, size_t n4)
{
    size_t i = (size_t)blockIdx.x * blockDim.x + threadIdx.x;
    if (i < n4) {
        float4 va = ((const float4*)a)[i];
        float4 vb = ((const float4*)b)[i];
        __half2 lo = __floats2half2_rn(va.x - vb.x, va.y - vb.y);
        __half2 hi = __floats2half2_rn(va.z - vb.z, va.w - vb.w);
        ((uint2*)c)[i] = make_uint2(*(unsigned*)&lo, *(unsigned*)&hi);
    }
}

// ---------------- f32 -> f16 convert ----------------
__global__ void __launch_bounds__(256)
f2h_kernel(const float* __restrict__ src, __half* __restrict__ dst, size_t n4)
{
    size_t i = (size_t)blockIdx.x * blockDim.x + threadIdx.x;
    if (i < n4) {
        float4 v = ((const float4*)src)[i];
        __half2 lo = __floats2half2_rn(v.x, v.y);
        __half2 hi = __floats2half2_rn(v.z, v.w);
        ((uint2*)dst)[i] = make_uint2(*(unsigned*)&lo, *(unsigned*)&hi);
    }
}

// ---------------- v [B][N][D] f32 -> vT [B][D][N] fp16 ----------------
__global__ void __launch_bounds__(256)
transpose_f2h_kernel(const float* __restrict__ v, __half* __restrict__ vt)
{
    __shared__ float tile[32][33];
    int b  = blockIdx.z;
    int t0 = blockIdx.x * 32;   // token
    int d0 = blockIdx.y * 32;   // feature
    int tx = threadIdx.x & 31;
    int ty = threadIdx.x >> 5;  // 0..7
    const float* vb = v + (size_t)b * NN_ * DD;
    __half* vtb = vt + (size_t)b * DD * NN_;
    #pragma unroll
    for (int i = 0; i < 4; ++i)
        tile[ty + 8 * i][tx] = vb[(size_t)(t0 + ty + 8 * i) * DD + d0 + tx];
    __syncthreads();
    #pragma unroll
    for (int i = 0; i < 4; ++i)
        vtb[(size_t)(d0 + ty + 8 * i) * NN_ + t0 + tx] = __float2half_rn(tile[tx][ty + 8 * i]);
}

// ---------------- fp16 tensor-core GEMM (all NT / K-major) ----------------
// C[m,n] = alpha * sum_k A[m,k] * B[n,k]  (+bias[n]) (gelu) (+addend[m,n])
// OH: output fp16 (else fp32). 128x128 block tile, kTile=32 halves,
// 4-stage cp.async, 8 warps (2x4), warp tile 64x32 via mma.m16n8k16.f16.

#define STAGES 4
#define KT 32
#define ASTRH 40                         // smem row stride in halves (80B, 16B-aligned)
#define STAGE_HALVES (128 * ASTRH)       // 5120
#define SMEM_BYTES (STAGES * 2 * STAGE_HALVES * 2)   // 81920

__device__ __forceinline__ void cp_async16(void* s, const void* g) {
    unsigned sa = (unsigned)__cvta_generic_to_shared(s);
    asm volatile("cp.async.cg.shared.global [%0], [%1], 16;\n" :: "r"(sa), "l"(g));
}
__device__ __forceinline__ void cp_commit() { asm volatile("cp.async.commit_group;\n" ::: "memory"); }
template<int NW> __device__ __forceinline__ void cp_wait() {
    asm volatile("cp.async.wait_group %0;\n" :: "n"(NW) : "memory");
}
__device__ __forceinline__ void mma_f16(float c[4], const unsigned a[4], const unsigned b[2]) {
    asm volatile(
        "mma.sync.aligned.m16n8k16.row.col.f32.f16.f16.f32 "
        "{%0,%1,%2,%3}, {%4,%5,%6,%7}, {%8,%9}, {%0,%1,%2,%3};"
        : "+f"(c[0]), "+f"(c[1]), "+f"(c[2]), "+f"(c[3])
        : "r"(a[0]), "r"(a[1]), "r"(a[2]), "r"(a[3]), "r"(b[0]), "r"(b[1]));
}

template<bool OH>
__global__ void __launch_bounds__(256, 2)
gemm_h(const __half* __restrict__ A, const __half* __restrict__ B,
       void* __restrict__ Cv,
       int M, int N, int K,
       size_t sA, size_t sB, size_t sC,
       float alpha,
       const float* __restrict__ bias,
       const float* __restrict__ addend,
       int do_gelu)
{
    extern __shared__ __half smem[];
    __half* As = smem;
    __half* Bs = smem + STAGES * STAGE_HALVES;

    const int t    = threadIdx.x;
    const int lane = t & 31;
    const int wid  = t >> 5;
    const int mBase = (wid & 1) * 64;
    const int nBase = (wid >> 1) * 32;
    const int grp   = lane >> 2;   // 0..7
    const int tig   = lane & 3;    // 0..3

    const int m0 = blockIdx.y * 128;
    const int n0 = blockIdx.x * 128;
    const __half* Ab = A + (size_t)blockIdx.z * sA;
    const __half* Bp = B + (size_t)blockIdx.z * sB;

    float acc[4][4][4];
    #pragma unroll
    for (int i = 0; i < 4; ++i)
        #pragma unroll
        for (int j = 0; j < 4; ++j)
            #pragma unroll
            for (int r = 0; r < 4; ++r) acc[i][j][r] = 0.f;

    const int nk = K / KT;

    auto load_tile = [&](int kt, int s) {
        const int kb = kt * KT;
        __half* Ad = As + s * STAGE_HALVES;
        __half* Bd = Bs + s * STAGE_HALVES;
        #pragma unroll
        for (int l = 0; l < 2; ++l) {
            int idx = t + l * 256;
            int m = idx >> 2, kc = (idx & 3) << 3;
            cp_async16(Ad + m * ASTRH + kc, Ab + (size_t)(m0 + m) * K + kb + kc);
        }
        #pragma unroll
        for (int l = 0; l < 2; ++l) {
            int idx = t + l * 256;
            int n = idx >> 2, kc = (idx & 3) << 3;
            cp_async16(Bd + n * ASTRH + kc, Bp + (size_t)(n0 + n) * K + kb + kc);
        }
    };

    #pragma unroll
    for (int i = 0; i < STAGES - 1; ++i) {
        if (i < nk) load_tile(i, i);
        cp_commit();
    }

    for (int kt = 0; kt < nk; ++kt) {
        const int ktn = kt + STAGES - 1;
        if (ktn < nk) load_tile(ktn, ktn % STAGES);
        cp_commit();

        cp_wait<STAGES - 2>();
        __syncthreads();

        const int s = kt % STAGES;
        const __half* Asb = As + s * STAGE_HALVES;
        const __half* Bsb = Bs + s * STAGE_HALVES;

        #pragma unroll
        for (int s16 = 0; s16 < 2; ++s16) {
            const int kk = s16 * 16 + 2 * tig;
            unsigned af[4][4], bf[4][2];
            #pragma unroll
            for (int mt = 0; mt < 4; ++mt) {
                int r = mBase + mt * 16 + grp;
                af[mt][0] = *(const unsigned*)(Asb + r * ASTRH + kk);
                af[mt][1] = *(const unsigned*)(Asb + (r + 8) * ASTRH + kk);
                af[mt][2] = *(const unsigned*)(Asb + r * ASTRH + kk + 8);
                af[mt][3] = *(const unsigned*)(Asb + (r + 8) * ASTRH + kk + 8);
            }
            #pragma unroll
            for (int nt = 0; nt < 4; ++nt) {
                int n = nBase + nt * 8 + grp;
                bf[nt][0] = *(const unsigned*)(Bsb + n * ASTRH + kk);
                bf[nt][1] = *(const unsigned*)(Bsb + n * ASTRH + kk + 8);
            }
            #pragma unroll
            for (int mt = 0; mt < 4; ++mt)
                #pragma unroll
                for (int nt = 0; nt < 4; ++nt)
                    mma_f16(acc[mt][nt], af[mt], bf[nt]);
        }
        __syncthreads();
    }

    // ---- epilogue: alpha -> +bias -> gelu -> +addend -> store ----
    #pragma unroll
    for (int mt = 0; mt < 4; ++mt) {
        int r0 = m0 + mBase + mt * 16 + grp;
        #pragma unroll
        for (int nt = 0; nt < 4; ++nt) {
            int c0 = n0 + nBase + nt * 8 + 2 * tig;
            float v00 = acc[mt][nt][0] * alpha;
            float v01 = acc[mt][nt][1] * alpha;
            float v10 = acc[mt][nt][2] * alpha;
            float v11 = acc[mt][nt][3] * alpha;
            if (bias) {
                float bv0 = bias[c0], bv1 = bias[c0 + 1];
                v00 += bv0; v01 += bv1; v10 += bv0; v11 += bv1;
            }
            if (do_gelu) {
                v00 = 0.5f * v00 * (1.0f + erff(v00 * 0.7071067811865475f));
                v01 = 0.5f * v01 * (1.0f + erff(v01 * 0.7071067811865475f));
                v10 = 0.5f * v10 * (1.0f + erff(v10 * 0.7071067811865475f));
                v11 = 0.5f * v11 * (1.0f + erff(v11 * 0.7071067811865475f));
            }
            if (addend) {
                const float* Ad = addend + (size_t)blockIdx.z * sC;
                v00 += Ad[(size_t)r0 * N + c0];
                v01 += Ad[(size_t)r0 * N + c0 + 1];
                v10 += Ad[(size_t)(r0 + 8) * N + c0];
                v11 += Ad[(size_t)(r0 + 8) * N + c0 + 1];
            }
            if (OH) {
                __half* Cb = (__half*)Cv + (size_t)blockIdx.z * sC;
                __half2 a2 = __floats2half2_rn(v00, v01);
                __half2 b2 = __floats2half2_rn(v10, v11);
                *(__half2*)(Cb + (size_t)r0 * N + c0)       = a2;
                *(__half2*)(Cb + (size_t)(r0 + 8) * N + c0) = b2;
            } else {
                float* Cb = (float*)Cv + (size_t)blockIdx.z * sC;
                Cb[(size_t)r0 * N + c0]           = v00;
                Cb[(size_t)r0 * N + c0 + 1]       = v01;
                Cb[(size_t)(r0 + 8) * N + c0]     = v10;
                Cb[(size_t)(r0 + 8) * N + c0 + 1] = v11;
            }
        }
    }
}

// ---------------- launch ----------------
extern "C" void kernel_launch(void* const* d_in, const int* in_sizes, int n_in,
                              void* d_out, int out_size)
{
    const float* q      = (const float*)d_in[0];
    const float* k      = (const float*)d_in[1];
    const float* v      = (const float*)d_in[2];
    const float* W_diff = (const float*)d_in[3];
    const float* b_diff = (const float*)d_in[4];
    const float* ln_g   = (const float*)d_in[5];
    const float* ln_b   = (const float*)d_in[6];
    const float* W1     = (const float*)d_in[7];
    const float* b1     = (const float*)d_in[8];
    const float* W2     = (const float*)d_in[9];
    const float* b2     = (const float*)d_in[10];
    float* out = (float*)d_out;

    float *pAttn, *pAf, *pFd, *pOut;
    __half *pX, *pL, *pVt, *pAttnH, *pVd, *pH, *pAct, *pWd, *pW1, *pW2;
    cudaGetSymbolAddress((void**)&pAttn,  g_attn);
    cudaGetSymbolAddress((void**)&pAf,    g_af);
    cudaGetSymbolAddress((void**)&pFd,    g_fd);
    cudaGetSymbolAddress((void**)&pOut,   g_out);
    cudaGetSymbolAddress((void**)&pX,     g_hX);
    cudaGetSymbolAddress((void**)&pL,     g_hL);
    cudaGetSymbolAddress((void**)&pVt,    g_hVt);
    cudaGetSymbolAddress((void**)&pAttnH, g_attnh);
    cudaGetSymbolAddress((void**)&pVd,    g_hVd);
    cudaGetSymbolAddress((void**)&pH,     g_hH);
    cudaGetSymbolAddress((void**)&pAct,   g_hAct);
    cudaGetSymbolAddress((void**)&pWd,    g_hWd);
    cudaGetSymbolAddress((void**)&pW1,    g_hW1);
    cudaGetSymbolAddress((void**)&pW2,    g_hW2);

    cudaFuncSetAttribute(gemm_h<false>, cudaFuncAttributeMaxDynamicSharedMemorySize, SMEM_BYTES);
    cudaFuncSetAttribute(gemm_h<true>,  cudaFuncAttributeMaxDynamicSharedMemorySize, SMEM_BYTES);

    const size_t sND = (size_t)NN_ * DD;
    const size_t sNN = (size_t)NN_ * NN_;

    // 0) weights -> fp16
    f2h_kernel<<<(DD * DD / 4 + 255) / 256, 256>>>(W_diff, pWd, (size_t)DD * DD / 4);
    f2h_kernel<<<(unsigned)(((size_t)HH * DD / 4 + 255) / 256), 256>>>(W1, pW1, (size_t)HH * DD / 4);
    f2h_kernel<<<(unsigned)(((size_t)HH * DD / 4 + 255) / 256), 256>>>(W2, pW2, (size_t)HH * DD / 4);

    // 0b) v -> vT fp16 [B][D][N]
    transpose_f2h_kernel<<<dim3(NN_ / 32, DD / 32, BB), 256>>>(v, pVt);

    // 1) q_prob/k_prob -> X(*1024), L (fp16)
    prob_kernel<<<BN, 256>>>(q, k, pX, pL);

    // 2) sid logits: attn = -(X @ L^T) / (32*1024)  (batched NT, f32 out)
    gemm_h<false><<<dim3(NN_ / 128, NN_ / 128, BB), 256, SMEM_BYTES>>>(
        pX, pL, pAttn, NN_, NN_, DD, sND, sND, sNN,
        -1.0f / 32768.0f, nullptr, nullptr, 0);

    // 3) softmax rows -> fp16 attn
    softmax_kernel<<<BN, 512>>>(pAttn, pAttnH);

    // 4) attn_feat = attn @ vT^T  (NT with B = vT[d][token]; f32 out)
    gemm_h<false><<<dim3(DD / 128, NN_ / 128, BB), 256, SMEM_BYTES>>>(
        pAttnH, pVt, pAf, NN_, DD, NN_, sNN, sND, sND,
        1.0f, nullptr, nullptr, 0);

    // 5) vd = half(v - attn_feat)
    {
        size_t n4 = (size_t)BN * DD / 4;
        sub_h_kernel<<<(unsigned)((n4 + 255) / 256), 256>>>(v, pAf, pVd, n4);
    }

    // 6) f_diff = vd @ W_diff^T + b_diff + q  (f32 out)
    gemm_h<false><<<dim3(DD / 128, BN / 128, 1), 256, SMEM_BYTES>>>(
        pVd, pWd, pFd, BN, DD, DD, 0, 0, 0,
        1.0f, b_diff, q, 0);

    // 7) h = LN(f_diff) -> fp16
    layernorm_kernel<<<BN, 256>>>(pFd, ln_g, ln_b, pH, 1);

    // 8) act = gelu(h @ W1^T + b1) -> fp16
    gemm_h<true><<<dim3(HH / 128, BN / 128, 1), 256, SMEM_BYTES>>>(
        pH, pW1, pAct, BN, HH, DD, 0, 0, 0,
        1.0f, b1, nullptr, 1);

    // 9) out_pre = act @ W2^T + b2 + f_diff  (f32 out)
    gemm_h<false><<<dim3(DD / 128, BN / 128, 1), 256, SMEM_BYTES>>>(
        pAct, pW2, pOut, BN, DD, HH, 0, 0, 0,
        1.0f, b2, pFd, 0);

    // 10) final LN -> d_out (f32)
    layernorm_kernel<<<BN, 256>>>(pOut, ln_g, ln_b, out, 0);
}